// round 2
// baseline (speedup 1.0000x reference)
#include <cuda_runtime.h>

#define H 128
#define NP_MAX 100000
#define NA_MAX 50000

// ---------------- scratch (static device globals; no allocation) ----------------
__device__ float g_aggC[NP_MAX * H];   // cites  -> paper accumulator
__device__ float g_aggW[NP_MAX * H];   // writes -> paper accumulator
__device__ float g_aggA[NA_MAX * H];   // rev    -> author accumulator
__device__ float g_invC[NP_MAX];       // 1/max(deg,1) per edge type
__device__ float g_invW[NP_MAX];
__device__ float g_invA[NA_MAX];
__device__ float g_xp[NP_MAX * H];     // layer-1 paper output
__device__ float g_xa[NA_MAX * H];     // layer-1 author output

// ---------------- zero fill ----------------
__global__ void zero_kernel(float* __restrict__ p, int n4) {
  int i = blockIdx.x * blockDim.x + threadIdx.x;
  if (i < n4) ((float4*)p)[i] = make_float4(0.f, 0.f, 0.f, 0.f);
}

// ---------------- degree count (once; edges identical across layers) ----------------
__global__ void count_kernel(const int* __restrict__ dst, float* __restrict__ cnt, int E) {
  int i = blockIdx.x * blockDim.x + threadIdx.x;
  if (i < E) atomicAdd(cnt + __ldg(dst + i), 1.0f);
}

__global__ void recip_kernel(float* __restrict__ cnt, int N) {
  int i = blockIdx.x * blockDim.x + threadIdx.x;
  if (i < N) cnt[i] = 1.0f / fmaxf(cnt[i], 1.0f);
}

// ---------------- edge scatter: warp per edge ----------------
__global__ void scatter_kernel(const float* __restrict__ xsrc,
                               const int* __restrict__ src,
                               const int* __restrict__ dst,
                               float* __restrict__ agg, int E) {
  int w = (blockIdx.x * blockDim.x + threadIdx.x) >> 5;
  int lane = threadIdx.x & 31;
  if (w >= E) return;
  int s = __ldg(src + w);
  int d = __ldg(dst + w);
  float4 v = __ldg((const float4*)(xsrc + (size_t)s * H) + lane);
#if __CUDA_ARCH__ >= 900
  atomicAdd(((float4*)(agg + (size_t)d * H)) + lane, v);
#else
  float* a = agg + (size_t)d * H + lane * 4;
  atomicAdd(a + 0, v.x); atomicAdd(a + 1, v.y);
  atomicAdd(a + 2, v.z); atomicAdd(a + 3, v.w);
#endif
}

// ---------------- combine helpers ----------------
// Tile loaders: 64 rows x 128 cols into smem (float4 per thread-iter).
__device__ __forceinline__ void load_mean_tile(float* __restrict__ sA,
                                               const float* __restrict__ agg,
                                               const float* __restrict__ inv,
                                               int row0, int N, int tid) {
  for (int idx = tid; idx < 64 * 32; idx += 256) {
    int row = idx >> 5;
    int r = row0 + row;
    float4 v = make_float4(0.f, 0.f, 0.f, 0.f);
    if (r < N) {
      float iv = __ldg(inv + r);
      float4 a = __ldg((const float4*)(agg + (size_t)r * H) + (idx & 31));
      v = make_float4(a.x * iv, a.y * iv, a.z * iv, a.w * iv);
    }
    ((float4*)sA)[idx] = v;
  }
}

__device__ __forceinline__ void load_tile(float* __restrict__ sA,
                                          const float* __restrict__ x,
                                          int row0, int N, int tid) {
  for (int idx = tid; idx < 64 * 32; idx += 256) {
    int row = idx >> 5;
    int r = row0 + row;
    float4 v = make_float4(0.f, 0.f, 0.f, 0.f);
    if (r < N) v = __ldg((const float4*)(x + (size_t)r * H) + (idx & 31));
    ((float4*)sA)[idx] = v;
  }
}

// acc[8][4] = mean @ Wl + bl + x @ Wr  for this thread's 8 rows x 4 cols.
__device__ __forceinline__ void sage_compute(float acc[8][4],
                                             const float* __restrict__ sAm,
                                             const float* __restrict__ sAx,
                                             float* __restrict__ sWl,
                                             float* __restrict__ sWr,
                                             const float* __restrict__ Wl,
                                             const float* __restrict__ bl,
                                             const float* __restrict__ Wr,
                                             int tid, int tx, int ty) {
  float4 b = __ldg(((const float4*)bl) + tx);
#pragma unroll
  for (int i = 0; i < 8; i++) {
    acc[i][0] = b.x; acc[i][1] = b.y; acc[i][2] = b.z; acc[i][3] = b.w;
  }
  for (int kc = 0; kc < 4; kc++) {
    const float4* gWl = (const float4*)(Wl + kc * 32 * H);
    const float4* gWr = (const float4*)(Wr + kc * 32 * H);
    for (int idx = tid; idx < 32 * H / 4; idx += 256) {
      ((float4*)sWl)[idx] = __ldg(gWl + idx);
      ((float4*)sWr)[idx] = __ldg(gWr + idx);
    }
    __syncthreads();
#pragma unroll 8
    for (int kk = 0; kk < 32; kk++) {
      int k = kc * 32 + kk;
      float4 wl = ((const float4*)(sWl + kk * H))[tx];
      float4 wr = ((const float4*)(sWr + kk * H))[tx];
#pragma unroll
      for (int i = 0; i < 8; i++) {
        float am = sAm[(ty * 8 + i) * H + k];   // warp-broadcast LDS
        float ax = sAx[(ty * 8 + i) * H + k];
        acc[i][0] += am * wl.x + ax * wr.x;
        acc[i][1] += am * wl.y + ax * wr.y;
        acc[i][2] += am * wl.z + ax * wr.z;
        acc[i][3] += am * wl.w + ax * wr.w;
      }
    }
    __syncthreads();
  }
}

// res += wgt * acc / max(||row||, 1e-12); full row lives across the 32 lanes of a warp.
__device__ __forceinline__ void norm_accum(float acc[8][4], float res[8][4], float wgt) {
#pragma unroll
  for (int i = 0; i < 8; i++) {
    float ss = acc[i][0] * acc[i][0] + acc[i][1] * acc[i][1] +
               acc[i][2] * acc[i][2] + acc[i][3] * acc[i][3];
#pragma unroll
    for (int o = 16; o > 0; o >>= 1) ss += __shfl_xor_sync(0xffffffffu, ss, o);
    float rn = wgt / fmaxf(sqrtf(ss), 1e-12f);
    res[i][0] += acc[i][0] * rn;
    res[i][1] += acc[i][1] * rn;
    res[i][2] += acc[i][2] * rn;
    res[i][3] += acc[i][3] * rn;
  }
}

// ---------------- paper combine: two sages, hetero-mean, relu ----------------
__global__ __launch_bounds__(256, 1) void combine_paper(
    const float* __restrict__ xd,
    const float* __restrict__ aggC, const float* __restrict__ invC,
    const float* __restrict__ aggW, const float* __restrict__ invW,
    const float* __restrict__ Wl1, const float* __restrict__ bl1, const float* __restrict__ Wr1,
    const float* __restrict__ Wl2, const float* __restrict__ bl2, const float* __restrict__ Wr2,
    float* __restrict__ out, int N) {
  extern __shared__ float smem[];
  float* sA1 = smem;                 // mean(cites)   64x128
  float* sA2 = sA1 + 64 * H;         // mean(writes)  64x128
  float* sA3 = sA2 + 64 * H;         // x_dst         64x128
  float* sWl = sA3 + 64 * H;         // 32x128
  float* sWr = sWl + 32 * H;         // 32x128

  int tid = threadIdx.x;
  int tx = tid & 31, ty = tid >> 5;
  int row0 = blockIdx.x * 64;

  load_mean_tile(sA1, aggC, invC, row0, N, tid);
  load_mean_tile(sA2, aggW, invW, row0, N, tid);
  load_tile(sA3, xd, row0, N, tid);
  __syncthreads();

  float acc[8][4], res[8][4];
#pragma unroll
  for (int i = 0; i < 8; i++) {
    res[i][0] = 0.f; res[i][1] = 0.f; res[i][2] = 0.f; res[i][3] = 0.f;
  }

  sage_compute(acc, sA1, sA3, sWl, sWr, Wl1, bl1, Wr1, tid, tx, ty);
  norm_accum(acc, res, 0.5f);
  sage_compute(acc, sA2, sA3, sWl, sWr, Wl2, bl2, Wr2, tid, tx, ty);
  norm_accum(acc, res, 0.5f);

#pragma unroll
  for (int i = 0; i < 8; i++) {
    int r = row0 + ty * 8 + i;
    if (r < N) {
      float4 o = make_float4(fmaxf(res[i][0], 0.f), fmaxf(res[i][1], 0.f),
                             fmaxf(res[i][2], 0.f), fmaxf(res[i][3], 0.f));
      ((float4*)(out + (size_t)r * H))[tx] = o;
    }
  }
}

// ---------------- author combine: one sage, relu ----------------
__global__ __launch_bounds__(256, 1) void combine_author(
    const float* __restrict__ xd,
    const float* __restrict__ aggR, const float* __restrict__ invR,
    const float* __restrict__ Wl1, const float* __restrict__ bl1, const float* __restrict__ Wr1,
    float* __restrict__ out, int N) {
  extern __shared__ float smem[];
  float* sA1 = smem;                 // mean(rev)  64x128
  float* sA3 = sA1 + 64 * H;         // x_dst      64x128
  float* sWl = sA3 + 64 * H;
  float* sWr = sWl + 32 * H;

  int tid = threadIdx.x;
  int tx = tid & 31, ty = tid >> 5;
  int row0 = blockIdx.x * 64;

  load_mean_tile(sA1, aggR, invR, row0, N, tid);
  load_tile(sA3, xd, row0, N, tid);
  __syncthreads();

  float acc[8][4], res[8][4];
#pragma unroll
  for (int i = 0; i < 8; i++) {
    res[i][0] = 0.f; res[i][1] = 0.f; res[i][2] = 0.f; res[i][3] = 0.f;
  }

  sage_compute(acc, sA1, sA3, sWl, sWr, Wl1, bl1, Wr1, tid, tx, ty);
  norm_accum(acc, res, 1.0f);

#pragma unroll
  for (int i = 0; i < 8; i++) {
    int r = row0 + ty * 8 + i;
    if (r < N) {
      float4 o = make_float4(fmaxf(res[i][0], 0.f), fmaxf(res[i][1], 0.f),
                             fmaxf(res[i][2], 0.f), fmaxf(res[i][3], 0.f));
      ((float4*)(out + (size_t)r * H))[tx] = o;
    }
  }
}

// ---------------- launch ----------------
extern "C" void kernel_launch(void* const* d_in, const int* in_sizes, int n_in,
                              void* d_out, int out_size) {
  const float* x_paper = (const float*)d_in[0];
  const float* x_author = (const float*)d_in[1];
  const int* cs = (const int*)d_in[2];
  const int* cd = (const int*)d_in[3];
  const int* ws = (const int*)d_in[4];
  const int* wd = (const int*)d_in[5];
  const int* rs = (const int*)d_in[6];
  const int* rd = (const int*)d_in[7];
  const float* P[18];
  for (int i = 0; i < 18; i++) P[i] = (const float*)d_in[8 + i];

  int NPn = in_sizes[0] / H;   // 100000
  int NAn = in_sizes[1] / H;   // 50000
  int EC = in_sizes[2];        // 1000000
  int EW = in_sizes[4];        // 320000
  int ER = in_sizes[6];        // 320000

  float *aggC, *aggW, *aggA, *invC, *invW, *invA, *xp1, *xa1;
  cudaGetSymbolAddress((void**)&aggC, g_aggC);
  cudaGetSymbolAddress((void**)&aggW, g_aggW);
  cudaGetSymbolAddress((void**)&aggA, g_aggA);
  cudaGetSymbolAddress((void**)&invC, g_invC);
  cudaGetSymbolAddress((void**)&invW, g_invW);
  cudaGetSymbolAddress((void**)&invA, g_invA);
  cudaGetSymbolAddress((void**)&xp1, g_xp);
  cudaGetSymbolAddress((void**)&xa1, g_xa);

  const size_t SMEM_P = (size_t)(3 * 64 * H + 2 * 32 * H) * sizeof(float);  // 128 KB
  const size_t SMEM_A = (size_t)(2 * 64 * H + 2 * 32 * H) * sizeof(float);  // 96 KB
  cudaFuncSetAttribute((const void*)combine_paper,
                       cudaFuncAttributeMaxDynamicSharedMemorySize, (int)SMEM_P);
  cudaFuncSetAttribute((const void*)combine_author,
                       cudaFuncAttributeMaxDynamicSharedMemorySize, (int)SMEM_A);

  // ---- degrees: edges identical across layers, compute once ----
  {
    int n4;
    n4 = NPn / 4;
    zero_kernel<<<(n4 + 255) / 256, 256>>>(invC, n4);
    zero_kernel<<<(n4 + 255) / 256, 256>>>(invW, n4);
    n4 = NAn / 4;
    zero_kernel<<<(n4 + 255) / 256, 256>>>(invA, n4);
    count_kernel<<<(EC + 255) / 256, 256>>>(cd, invC, EC);
    count_kernel<<<(EW + 255) / 256, 256>>>(wd, invW, EW);
    count_kernel<<<(ER + 255) / 256, 256>>>(rd, invA, ER);
    recip_kernel<<<(NPn + 255) / 256, 256>>>(invC, NPn);
    recip_kernel<<<(NPn + 255) / 256, 256>>>(invW, NPn);
    recip_kernel<<<(NAn + 255) / 256, 256>>>(invA, NAn);
  }

  const float* xp_in = x_paper;
  const float* xa_in = x_author;

  for (int l = 0; l < 2; l++) {
    int n4;
    n4 = NPn * H / 4;
    zero_kernel<<<(n4 + 255) / 256, 256>>>(aggC, n4);
    zero_kernel<<<(n4 + 255) / 256, 256>>>(aggW, n4);
    n4 = NAn * H / 4;
    zero_kernel<<<(n4 + 255) / 256, 256>>>(aggA, n4);

    scatter_kernel<<<(EC + 7) / 8, 256>>>(xp_in, cs, cd, aggC, EC);
    scatter_kernel<<<(EW + 7) / 8, 256>>>(xa_in, ws, wd, aggW, EW);
    scatter_kernel<<<(ER + 7) / 8, 256>>>(xp_in, rs, rd, aggA, ER);

    const float* const* q = P + l * 9;  // cites(Wl,bl,Wr), writes(Wl,bl,Wr), rev(Wl,bl,Wr)
    float* outp = (l == 1) ? (float*)d_out : xp1;
    float* outa = (l == 1) ? ((float*)d_out + (size_t)NPn * H) : xa1;

    combine_paper<<<(NPn + 63) / 64, 256, SMEM_P>>>(
        xp_in, aggC, invC, aggW, invW,
        q[0], q[1], q[2], q[3], q[4], q[5], outp, NPn);
    combine_author<<<(NAn + 63) / 64, 256, SMEM_A>>>(
        xa_in, aggA, invA, q[6], q[7], q[8], outa, NAn);

    xp_in = xp1;
    xa_in = xa1;
  }
}